// round 7
// baseline (speedup 1.0000x reference)
#include <cuda_runtime.h>
#include <cstdint>

#define NVEH 16384
#define NT   256
#define H    20

#define VPC  64                 // vehicles per CTA
#define TPC  160                // 8 groups x 20 units
#define NCTA (NVEH / VPC)       // 256
#define VPT  8                  // vehicles per thread

typedef unsigned long long ull;

// Packed per-unit weights (stride 48 per unit):
//   [0..19]  IF pairs for U rows (x0.5 prescale, sigmoid gates)
//   [20..22] IF pairs for W rows (x0.5)
//   [23]     IF bias (x0.5)
//   [24..43] GO pairs for U rows (g x1, o x0.5)
//   [44..46] GO pairs for W rows
//   [47]     GO bias
__device__ float2 gWt[20 * 48];
__device__ float  gWd[24];      // Wd[0..19] (pair-packable), bd at [20]

// ---------- packed f32x2 helpers (sm_103a) ----------
__device__ __forceinline__ void ffma2(ull& d, ull a, ull b) {
    asm("fma.rn.f32x2 %0, %1, %2, %0;" : "+l"(d) : "l"(a), "l"(b));
}
__device__ __forceinline__ ull dup2(float x) {
    ull r; asm("mov.b64 %0, {%1, %1};" : "=l"(r) : "f"(x)); return r;
}
__device__ __forceinline__ ull pack2(float lo, float hi) {
    ull r; asm("mov.b64 %0, {%1, %2};" : "=l"(r) : "f"(lo), "f"(hi)); return r;
}
__device__ __forceinline__ ull add2(ull a, ull b) {
    ull r; asm("add.rn.f32x2 %0, %1, %2;" : "=l"(r) : "l"(a), "l"(b)); return r;
}
__device__ __forceinline__ float lo32(ull v) {
    float f; asm("{ .reg .b32 hi; mov.b64 {%0, hi}, %1; }" : "=f"(f) : "l"(v)); return f;
}
__device__ __forceinline__ float hi32(ull v) {
    float f; asm("{ .reg .b32 lo; mov.b64 {lo, %0}, %1; }" : "=f"(f) : "l"(v)); return f;
}

// ---------- HW tanh (MUFU.TANH) ----------
__device__ __forceinline__ float fast_tanh(float x) {
    float y; asm("tanh.approx.f32 %0, %1;" : "=f"(y) : "f"(x)); return y;
}
// gate weights pre-scaled by 0.5 -> sig(z) = 0.5*tanh(acc) + 0.5
__device__ __forceinline__ float sig_from_half(float acc_half) {
    return fmaf(0.5f, fast_tanh(acc_half), 0.5f);
}

// Bank-swizzled smem row offset (floats), 16B aligned; row holds 20 h values.
__device__ __forceinline__ int rowoff(int v) {
    return v * 24 + ((v >> 2) & 1) * 4 + (v >> 3) * 8;
}

// ---------- repack kernel ----------
__global__ void repack_kernel(const float* __restrict__ W,
                              const float* __restrict__ U,
                              const float* __restrict__ b,
                              const float* __restrict__ Wd,
                              const float* __restrict__ bd)
{
    int i = blockIdx.x * blockDim.x + threadIdx.x;
    if (i < 20 * 48) {
        int u = i / 48, s = i % 48;
        float a0, a1;
        if (s < 24) {                       // IF pair
            const float* row = (s < 20) ? (U + s * 80)
                             : (s < 23) ? (W + (s - 20) * 80)
                             : b;
            a0 = 0.5f * row[u];             // i gate
            a1 = 0.5f * row[20 + u];        // f gate
        } else {                            // GO pair
            int k = s - 24;
            const float* row = (k < 20) ? (U + k * 80)
                             : (k < 23) ? (W + (k - 20) * 80)
                             : b;
            a0 = row[40 + u];               // g gate (tanh, full)
            a1 = 0.5f * row[60 + u];        // o gate
        }
        gWt[i] = make_float2(a0, a1);
    }
    if (i < 20)  gWd[i]  = Wd[i];
    if (i == 20) gWd[20] = bd[0];
    if (i > 20 && i < 24) gWd[i] = 0.f;
}

__global__ __launch_bounds__(TPC, 2)
void rnncf_kernel(const float* __restrict__ lead_inputs,  // (NVEH, NT, 2)
                  const float* __restrict__ init_state,   // (NVEH, 2)
                  const float* __restrict__ h0,           // (NVEH, H)
                  const float* __restrict__ c0,           // (NVEH, H)
                  float* __restrict__ out,
                  int out_size)
{
    // Double-buffered h rows only (x no longer lives in smem).
    __shared__ float hbuf[2][1600];

    const int tid   = threadIdx.x;
    const int u     = tid % 20;
    const int grp   = tid / 20;
    const int vb    = grp * VPT;
    const int gbase = blockIdx.x * VPC + vb;

    // ---- unit weights into registers (whole sim) ----
    ull wIF[23], wGO[23], bIF, bGO;
    {
        const ull* tb = reinterpret_cast<const ull*>(gWt) + u * 48;
#pragma unroll
        for (int k = 0; k < 23; ++k) { wIF[k] = tb[k]; wGO[k] = tb[24 + k]; }
        bIF = tb[23]; bGO = tb[47];
    }
    // Wd as 10 packed pairs + bias (same for every thread)
    ull wdp[10];
    {
        const ull* wq = reinterpret_cast<const ull*>(gWd);
#pragma unroll
        for (int j = 0; j < 10; ++j) wdp[j] = wq[j];
    }
    const float bdv = gWd[20];
    const ull K01 = pack2(0.1f, 0.1f);

    // ---- init state (pos/spd packed per vehicle; redundant across 20 unit-threads) ----
    float cc[VPT];
    ull   ps[VPT];
#pragma unroll
    for (int v = 0; v < VPT; ++v) {
        int gveh = gbase + v;
        cc[v] = c0[gveh * H + u];
        hbuf[0][rowoff(vb + v) + u] = h0[gveh * H + u];
        ps[v] = pack2(init_state[2 * gveh], init_state[2 * gveh + 1]);
    }

    const float2* leadbase = reinterpret_cast<const float2*>(lead_inputs) + (size_t)gbase * NT;
    const bool write_extras = (out_size >= NT * NVEH + NVEH + 2 * NVEH * H);

#define KH(kk, val) { ull md = dup2(val); ffma2(ai, wIF[kk], md); ffma2(ag, wGO[kk], md); }

#pragma unroll 1
    for (int t = 0; t < NT; ++t) {
        // prefetch lead[t] for the 8 vehicles (L1-broadcast across unit-threads)
        float2 ld[VPT];
#pragma unroll
        for (int v = 0; v < VPT; ++v) ld[v] = leadbase[v * NT + t];

        __syncthreads();                    // h(t) visible in hbuf[t&1]
        const float* rb = hbuf[t & 1];
        float*       wb = hbuf[(t + 1) & 1];

#pragma unroll
        for (int v = 0; v < VPT; ++v) {
            const int ro = rowoff(vb + v);
            float4 h0_ = *reinterpret_cast<const float4*>(rb + ro);
            float4 h1_ = *reinterpret_cast<const float4*>(rb + ro + 4);
            float4 h2_ = *reinterpret_cast<const float4*>(rb + ro + 8);
            float4 h3_ = *reinterpret_cast<const float4*>(rb + ro + 12);
            float4 h4_ = *reinterpret_cast<const float4*>(rb + ro + 16);

            if (t > 0) {
                // p = Wd . h(t) + bd  (packed, two partial chains)
                ull pa = pack2(bdv, 0.f);
                ull pb = pack2(0.f, 0.f);
                ffma2(pa, pack2(h0_.x, h0_.y), wdp[0]);
                ffma2(pb, pack2(h0_.z, h0_.w), wdp[1]);
                ffma2(pa, pack2(h1_.x, h1_.y), wdp[2]);
                ffma2(pb, pack2(h1_.z, h1_.w), wdp[3]);
                ffma2(pa, pack2(h2_.x, h2_.y), wdp[4]);
                ffma2(pb, pack2(h2_.z, h2_.w), wdp[5]);
                ffma2(pa, pack2(h3_.x, h3_.y), wdp[6]);
                ffma2(pb, pack2(h3_.z, h3_.w), wdp[7]);
                ffma2(pa, pack2(h4_.x, h4_.y), wdp[8]);
                ffma2(pb, pack2(h4_.z, h4_.w), wdp[9]);
                ull pc = add2(pa, pb);
                float p = lo32(pc) + hi32(pc);
                float a = fmaf(7.0f, p, -4.0f);        // (MAXA-MINA)*out + MINA
                ffma2(ps[v], K01, dup2(a));            // {pos,spd} += 0.1*a
                if (u == 0)
                    out[(size_t)(t - 1) * NVEH + gbase + v] = lo32(ps[v]);
            }

            const float pos = lo32(ps[v]);
            const float spd = hi32(ps[v]);
            const float x0 = (ld[v].x - pos) * (1.0f / 100.0f);
            const float x1 = spd * (1.0f / 40.0f);
            const float x2 = ld[v].y * (1.0f / 40.0f);

            ull ai = bIF, ag = bGO;
            KH(0,  h0_.x) KH(1,  h0_.y) KH(2,  h0_.z) KH(3,  h0_.w)
            KH(4,  h1_.x) KH(5,  h1_.y) KH(6,  h1_.z) KH(7,  h1_.w)
            KH(8,  h2_.x) KH(9,  h2_.y) KH(10, h2_.z) KH(11, h2_.w)
            KH(12, h3_.x) KH(13, h3_.y) KH(14, h3_.z) KH(15, h3_.w)
            KH(16, h4_.x) KH(17, h4_.y) KH(18, h4_.z) KH(19, h4_.w)
            KH(20, x0) KH(21, x1) KH(22, x2)

            float si = sig_from_half(lo32(ai));
            float sf = sig_from_half(hi32(ai));
            float tg = fast_tanh(lo32(ag));
            float so = sig_from_half(hi32(ag));
            float cn = fmaf(sf, cc[v], si * tg);
            cc[v] = cn;
            wb[ro + u] = so * fast_tanh(cn);            // h(t+1)
        }
    }

    // ---- epilogue: final pos/spd update from h(NT), stores ----
    __syncthreads();
    const float* fb = hbuf[NT & 1];   // NT=256 even -> buf[0]
    float* hout = out + (size_t)NT * NVEH + NVEH;
    float* cout = hout + (size_t)NVEH * H;

#pragma unroll
    for (int v = 0; v < VPT; ++v) {
        const int ro = rowoff(vb + v);
        float4 h0_ = *reinterpret_cast<const float4*>(fb + ro);
        float4 h1_ = *reinterpret_cast<const float4*>(fb + ro + 4);
        float4 h2_ = *reinterpret_cast<const float4*>(fb + ro + 8);
        float4 h3_ = *reinterpret_cast<const float4*>(fb + ro + 12);
        float4 h4_ = *reinterpret_cast<const float4*>(fb + ro + 16);
        ull pa = pack2(bdv, 0.f);
        ull pb = pack2(0.f, 0.f);
        ffma2(pa, pack2(h0_.x, h0_.y), wdp[0]);
        ffma2(pb, pack2(h0_.z, h0_.w), wdp[1]);
        ffma2(pa, pack2(h1_.x, h1_.y), wdp[2]);
        ffma2(pb, pack2(h1_.z, h1_.w), wdp[3]);
        ffma2(pa, pack2(h2_.x, h2_.y), wdp[4]);
        ffma2(pb, pack2(h2_.z, h2_.w), wdp[5]);
        ffma2(pa, pack2(h3_.x, h3_.y), wdp[6]);
        ffma2(pb, pack2(h3_.z, h3_.w), wdp[7]);
        ffma2(pa, pack2(h4_.x, h4_.y), wdp[8]);
        ffma2(pb, pack2(h4_.z, h4_.w), wdp[9]);
        ull pc = add2(pa, pb);
        float p = lo32(pc) + hi32(pc);
        float a = fmaf(7.0f, p, -4.0f);
        ffma2(ps[v], K01, dup2(a));
        if (u == 0)
            out[(size_t)(NT - 1) * NVEH + gbase + v] = lo32(ps[v]);

        if (write_extras) {
            int gveh = gbase + v;
            if (u == 0) out[(size_t)NT * NVEH + gveh] = hi32(ps[v]);
            hout[gveh * H + u] = fb[ro + u];
            cout[gveh * H + u] = cc[v];
        }
    }
#undef KH
}

extern "C" void kernel_launch(void* const* d_in, const int* in_sizes, int n_in,
                              void* d_out, int out_size) {
    const float* lead_inputs = (const float*)d_in[0];
    const float* init_state  = (const float*)d_in[1];
    const float* h0          = (const float*)d_in[2];
    const float* c0          = (const float*)d_in[3];
    const float* W           = (const float*)d_in[4];
    const float* U           = (const float*)d_in[5];
    const float* b           = (const float*)d_in[6];
    const float* Wd          = (const float*)d_in[7];
    const float* bd          = (const float*)d_in[8];

    repack_kernel<<<1, 1024>>>(W, U, b, Wd, bd);
    rnncf_kernel<<<NCTA, TPC>>>(lead_inputs, init_state, h0, c0,
                                (float*)d_out, out_size);
}